// round 11
// baseline (speedup 1.0000x reference)
#include <cuda_runtime.h>
#include <cuda_bf16.h>
#include <cstdint>

// ---------------------------------------------------------------------------
// Shapes (fixed)
// ---------------------------------------------------------------------------
#define NTOK 4096            // B*T
#define HDIM 4096
#define SDIM 1024
#define FDIM 9984
#define KTAY 6144            // S*G

// ---------------------------------------------------------------------------
// Scratch (__device__ globals; allocation-free)
// ---------------------------------------------------------------------------
__device__ __nv_bfloat16 g_Xhi [NTOK * HDIM], g_Xlo [NTOK * HDIM];
__device__ __nv_bfloat16 g_upwh[SDIM * HDIM], g_upwl[SDIM * HDIM];
__device__ __nv_bfloat16 g_gwh [SDIM * HDIM], g_gwl [SDIM * HDIM];
__device__ __nv_bfloat16 g_laoh[HDIM * SDIM], g_laol[HDIM * SDIM];
__device__ __nv_bfloat16 g_fwh [HDIM * KTAY], g_fwl [HDIM * KTAY];
__device__ __nv_bfloat16 g_fgwh[(size_t)FDIM * HDIM], g_fgwl[(size_t)FDIM * HDIM];
__device__ __nv_bfloat16 g_fuwh[(size_t)FDIM * HDIM], g_fuwl[(size_t)FDIM * HDIM];
__device__ __nv_bfloat16 g_fdwh[(size_t)HDIM * FDIM], g_fdwl[(size_t)HDIM * FDIM];
__device__ float         g_AU  [NTOK * SDIM], g_GP  [NTOK * SDIM];
__device__ __nv_bfloat16 g_AUh [NTOK * SDIM], g_AUl [NTOK * SDIM];
__device__ __nv_bfloat16 g_TMPh[NTOK * KTAY], g_TMPl[NTOK * KTAY];
__device__ float         g_BG  [(size_t)NTOK * FDIM], g_BU[(size_t)NTOK * FDIM];
__device__ __nv_bfloat16 g_Ph  [(size_t)NTOK * FDIM], g_Pl[(size_t)NTOK * FDIM];

// ---------------------------------------------------------------------------
// Baseline-PTX helpers
// ---------------------------------------------------------------------------
__device__ __forceinline__ uint32_t smem_u32(const void* p) {
    uint32_t a;
    asm("{ .reg .u64 t; cvta.to.shared.u64 t, %1; cvt.u32.u64 %0, t; }" : "=r"(a) : "l"(p));
    return a;
}
__device__ __forceinline__ void cpasync16(uint32_t dst, const void* src) {
    asm volatile("cp.async.cg.shared.global [%0], [%1], 16;" :: "r"(dst), "l"(src) : "memory");
}
__device__ __forceinline__ void cp_commit() {
    asm volatile("cp.async.commit_group;" ::: "memory");
}
template <int N>
__device__ __forceinline__ void cp_wait() {
    asm volatile("cp.async.wait_group %0;" :: "n"(N) : "memory");
}
__device__ __forceinline__ void ldm4(uint32_t* r, uint32_t a) {
    asm volatile("ldmatrix.sync.aligned.m8n8.x4.shared.b16 {%0,%1,%2,%3}, [%4];"
                 : "=r"(r[0]), "=r"(r[1]), "=r"(r[2]), "=r"(r[3]) : "r"(a));
}
__device__ __forceinline__ void mma16816(float* d, const uint32_t* a, uint32_t b0, uint32_t b1) {
    asm volatile("mma.sync.aligned.m16n8k16.row.col.f32.bf16.bf16.f32 "
                 "{%0,%1,%2,%3}, {%4,%5,%6,%7}, {%8,%9}, {%0,%1,%2,%3};"
                 : "+f"(d[0]), "+f"(d[1]), "+f"(d[2]), "+f"(d[3])
                 : "r"(a[0]), "r"(a[1]), "r"(a[2]), "r"(a[3]), "r"(b0), "r"(b1));
}
// packed fp32 -> bf16x2 (lo element in low half, per little-endian bf16 array)
__device__ __forceinline__ uint32_t cvt_bf16x2(float lo_el, float hi_el) {
    uint32_t r;
    asm("cvt.rn.bf16x2.f32 %0, %1, %2;" : "=r"(r) : "f"(hi_el), "f"(lo_el));
    return r;
}
__device__ __forceinline__ float bf_lo_f(uint32_t p) { return __uint_as_float(p << 16); }
__device__ __forceinline__ float bf_hi_f(uint32_t p) { return __uint_as_float(p & 0xffff0000u); }

// ---------------------------------------------------------------------------
// Split-bf16 tensor-core GEMM: C[N=4096, M] (+)= A[.,K] @ B[M,K]^T
// 3-pass: D = Ah*Bh + Ah*Bl + Al*Bh, fp32 accum (~1.7e-4 end-to-end).
// (2-pass variant measured at 1.74e-3 end-to-end in R10 -> over threshold;
//  do not re-enable without a tighter error budget.)
// CTA tile 128x128, BK=32, 256 threads (8 warps, 2x4), warp tile 64x32.
// 3-stage cp.async ring, ONE __syncthreads per k-block, 2 CTAs/SM.
// SMEM: unpadded 64B rows + XOR swizzle (chunk' = chunk ^ ((row>>1)&3)).
// Requires M%128==0, K%32==0.
// ---------------------------------------------------------------------------
#define BK        32
#define ROWB      64
#define SA_HI     0
#define SA_LO     (128 * ROWB)
#define SB_HI     (2 * 128 * ROWB)
#define SB_LO     (3 * 128 * ROWB)
#define STAGE_B   (4 * 128 * ROWB)         // 32768
#define NSTAGE    3
#define SMEM_TOTAL (NSTAGE * STAGE_B)      // 98304 (x2 CTAs = 192KB)

template <int BETA>
__global__ void __launch_bounds__(256, 2)
tc_gemm(const __nv_bfloat16* __restrict__ Ahi, const __nv_bfloat16* __restrict__ Alo,
        const __nv_bfloat16* __restrict__ Bhi, const __nv_bfloat16* __restrict__ Blo,
        float* __restrict__ C, int M, int K)
{
    extern __shared__ char smem[];
    const uint32_t sb = smem_u32(smem);
    const int t    = threadIdx.x;
    const int lane = t & 31;
    const int w    = t >> 5;
    const int wm   = w >> 2;
    const int wn   = w & 3;

    const size_t rs = (size_t)K * 2;
    const char* Ah = (const char*)Ahi + (size_t)blockIdx.y * 128 * rs;
    const char* Al = (const char*)Alo + (size_t)blockIdx.y * 128 * rs;
    const char* Bh = (const char*)Bhi + (size_t)blockIdx.x * 128 * rs;
    const char* Bl = (const char*)Blo + (size_t)blockIdx.x * 128 * rs;

    const int KB = K / BK;

    int r0 = t >> 2, c0 = t & 3;
    int r1 = r0 + 64;
    int cs = c0 ^ ((r0 >> 1) & 3);
    uint32_t so0 = (uint32_t)r0 * ROWB + cs * 16;
    uint32_t so1 = (uint32_t)r1 * ROWB + cs * 16;
    size_t   go0 = (size_t)r0 * rs + c0 * 16;
    size_t   go1 = (size_t)r1 * rs + c0 * 16;

#define LOAD_STAGE(kb, buf)                                                  \
    do {                                                                     \
        uint32_t st = sb + (uint32_t)(buf) * STAGE_B;                        \
        size_t   kofs = (size_t)(kb) * 64;                                   \
        cpasync16(st + SA_HI + so0, Ah + go0 + kofs);                        \
        cpasync16(st + SA_HI + so1, Ah + go1 + kofs);                        \
        cpasync16(st + SA_LO + so0, Al + go0 + kofs);                        \
        cpasync16(st + SA_LO + so1, Al + go1 + kofs);                        \
        cpasync16(st + SB_HI + so0, Bh + go0 + kofs);                        \
        cpasync16(st + SB_HI + so1, Bh + go1 + kofs);                        \
        cpasync16(st + SB_LO + so0, Bl + go0 + kofs);                        \
        cpasync16(st + SB_LO + so1, Bl + go1 + kofs);                        \
        cp_commit();                                                         \
    } while (0)

    const int la_r  = lane & 15;
    const int la_sw = (la_r >> 1) & 3;
    const int la_c  = lane >> 4;
    const int lb_r  = (lane & 7) + ((lane >> 4) << 3);
    const int lb_sw = (lb_r >> 1) & 3;
    const int lb_c  = (lane >> 3) & 1;

    float acc[4][4][4];
#pragma unroll
    for (int mi = 0; mi < 4; mi++)
#pragma unroll
        for (int ni = 0; ni < 4; ni++)
#pragma unroll
            for (int q = 0; q < 4; q++) acc[mi][ni][q] = 0.f;

    LOAD_STAGE(0, 0);
    LOAD_STAGE(1, 1);

    int buf = 0, nbuf = 2;
    for (int kb = 0; kb < KB; kb++) {
        if (kb + 1 < KB) cp_wait<1>(); else cp_wait<0>();
        __syncthreads();
        if (kb + 2 < KB) LOAD_STAGE(kb + 2, nbuf);

        const uint32_t st = sb + (uint32_t)buf * STAGE_B;
#pragma unroll
        for (int kk = 0; kk < 2; kk++) {
            const uint32_t ca = (uint32_t)((kk * 2 + la_c) ^ la_sw) * 16;
            const uint32_t cb = (uint32_t)((kk * 2 + lb_c) ^ lb_sw) * 16;
            uint32_t bhf[2][4], blf[2][4];
#pragma unroll
            for (int pr = 0; pr < 2; pr++) {
                uint32_t base = (uint32_t)(wn * 32 + pr * 16 + lb_r) * ROWB + cb;
                ldm4(bhf[pr], st + SB_HI + base);
                ldm4(blf[pr], st + SB_LO + base);
            }
#pragma unroll
            for (int mi = 0; mi < 4; mi++) {
                uint32_t ah[4], al[4];
                uint32_t base = (uint32_t)(wm * 64 + mi * 16 + la_r) * ROWB + ca;
                ldm4(ah, st + SA_HI + base);
                ldm4(al, st + SA_LO + base);
#pragma unroll
                for (int ni = 0; ni < 4; ni++) {
                    const int pr = ni >> 1, hf = (ni & 1) * 2;
                    mma16816(acc[mi][ni], ah, bhf[pr][hf], bhf[pr][hf + 1]);
                    mma16816(acc[mi][ni], ah, blf[pr][hf], blf[pr][hf + 1]);
                    mma16816(acc[mi][ni], al, bhf[pr][hf], bhf[pr][hf + 1]);
                }
            }
        }
        buf  = (buf  == 2) ? 0 : buf + 1;
        nbuf = (nbuf == 2) ? 0 : nbuf + 1;
    }

    // ---- epilogue ----
    const int erow = blockIdx.y * 128 + wm * 64 + (lane >> 2);
    const int ecol = blockIdx.x * 128 + wn * 32 + (lane & 3) * 2;
#pragma unroll
    for (int mi = 0; mi < 4; mi++) {
#pragma unroll
        for (int ni = 0; ni < 4; ni++) {
            float* p0 = C + (size_t)(erow + mi * 16) * M + ecol + ni * 8;
            float* p1 = p0 + 8 * M;
            float2 v0 = make_float2(acc[mi][ni][0], acc[mi][ni][1]);
            float2 v1 = make_float2(acc[mi][ni][2], acc[mi][ni][3]);
            if (BETA) {
                float2 o0 = *(float2*)p0, o1 = *(float2*)p1;
                v0.x += o0.x; v0.y += o0.y;
                v1.x += o1.x; v1.y += o1.y;
            }
            *(float2*)p0 = v0;
            *(float2*)p1 = v1;
        }
    }
#undef LOAD_STAGE
}

// ---------------------------------------------------------------------------
// fp32 -> (hi, lo) bf16 split. Unit = 2 float4 (8 elems) -> one 16B hi store
// + one 16B lo store, cvt.rn.bf16x2 (2 elems/instr). 4 units/thread.
// ---------------------------------------------------------------------------
__global__ void split8(const float4* __restrict__ src,
                       uint4* __restrict__ hi, uint4* __restrict__ lo, int n8)
{
    int u0 = blockIdx.x * (blockDim.x * 4) + threadIdx.x;
    float4 a[4], b[4];
    bool   ok[4];
#pragma unroll
    for (int j = 0; j < 4; j++) {
        int u = u0 + j * 256;
        ok[j] = (u < n8);
        if (ok[j]) { a[j] = src[2 * (size_t)u]; b[j] = src[2 * (size_t)u + 1]; }
    }
#pragma unroll
    for (int j = 0; j < 4; j++) {
        if (!ok[j]) continue;
        int u = u0 + j * 256;
        uint32_t h0 = cvt_bf16x2(a[j].x, a[j].y);
        uint32_t h1 = cvt_bf16x2(a[j].z, a[j].w);
        uint32_t h2 = cvt_bf16x2(b[j].x, b[j].y);
        uint32_t h3 = cvt_bf16x2(b[j].z, b[j].w);
        hi[u] = make_uint4(h0, h1, h2, h3);
        uint32_t l0 = cvt_bf16x2(a[j].x - bf_lo_f(h0), a[j].y - bf_hi_f(h0));
        uint32_t l1 = cvt_bf16x2(a[j].z - bf_lo_f(h1), a[j].w - bf_hi_f(h1));
        uint32_t l2 = cvt_bf16x2(b[j].x - bf_lo_f(h2), b[j].y - bf_hi_f(h2));
        uint32_t l3 = cvt_bf16x2(b[j].z - bf_lo_f(h3), b[j].w - bf_hi_f(h3));
        lo[u] = make_uint4(l0, l1, l2, l3);
    }
}

// ---------------------------------------------------------------------------
// Taylor coefficients -> split bf16 TMP[t, s*6+g]
// ---------------------------------------------------------------------------
__global__ void taylor_kernel(const float* __restrict__ AU, const float* __restrict__ GP,
                              const float* __restrict__ lp, const float* __restrict__ df,
                              __nv_bfloat16* __restrict__ TMPh, __nv_bfloat16* __restrict__ TMPl)
{
    int idx = blockIdx.x * blockDim.x + threadIdx.x;    // t*1024 + s
    if (idx >= NTOK * SDIM) return;
    int s = idx & (SDIM - 1);

    float au    = AU[idx];
    float delta = GP[idx] - lp[s];
    float neg   = (delta > 0.f) ? 1.f : -1.f;
    float ad    = fabsf(delta);
    float ld    = logf(ad);
    float keep  = (ad <= 2.5f) ? 1.f : 0.f;

    float v[6];
#pragma unroll
    for (int g = 0; g < 6; g++) {
        int   m = g + 1;
        float dterm = expf(ld * (float)m - df[g]);
        if (m & 1) dterm *= neg;
        float x = dterm * au;
        if (m > 4) x *= keep;
        v[g] = x;
    }
    uint32_t h[3], l[3];
#pragma unroll
    for (int q = 0; q < 3; q++) {
        h[q] = cvt_bf16x2(v[2 * q], v[2 * q + 1]);
        l[q] = cvt_bf16x2(v[2 * q] - bf_lo_f(h[q]), v[2 * q + 1] - bf_hi_f(h[q]));
    }
    uint32_t* ph = (uint32_t*)(TMPh + (size_t)idx * 6);
    uint32_t* pl = (uint32_t*)(TMPl + (size_t)idx * 6);
    ph[0] = h[0]; ph[1] = h[1]; ph[2] = h[2];
    pl[0] = l[0]; pl[1] = l[1]; pl[2] = l[2];
}

// ---------------------------------------------------------------------------
// P = silu(G) * U -> split bf16. Unit = 2 float4; 2 units/thread.
// ---------------------------------------------------------------------------
__global__ void silu_split8(const float4* __restrict__ G, const float4* __restrict__ U,
                            uint4* __restrict__ Ph, uint4* __restrict__ Pl, int n8)
{
    int u0 = blockIdx.x * (blockDim.x * 2) + threadIdx.x;
    float4 g[2][2], uu[2][2];
    bool   ok[2];
#pragma unroll
    for (int j = 0; j < 2; j++) {
        int u = u0 + j * 256;
        ok[j] = (u < n8);
        if (ok[j]) {
            g[j][0]  = G[2 * (size_t)u];     g[j][1]  = G[2 * (size_t)u + 1];
            uu[j][0] = U[2 * (size_t)u];     uu[j][1] = U[2 * (size_t)u + 1];
        }
    }
#pragma unroll
    for (int j = 0; j < 2; j++) {
        if (!ok[j]) continue;
        int u = u0 + j * 256;
        float p[8];
#pragma unroll
        for (int h = 0; h < 2; h++) {
            p[h * 4 + 0] = g[j][h].x / (1.f + expf(-g[j][h].x)) * uu[j][h].x;
            p[h * 4 + 1] = g[j][h].y / (1.f + expf(-g[j][h].y)) * uu[j][h].y;
            p[h * 4 + 2] = g[j][h].z / (1.f + expf(-g[j][h].z)) * uu[j][h].z;
            p[h * 4 + 3] = g[j][h].w / (1.f + expf(-g[j][h].w)) * uu[j][h].w;
        }
        uint32_t h0 = cvt_bf16x2(p[0], p[1]);
        uint32_t h1 = cvt_bf16x2(p[2], p[3]);
        uint32_t h2 = cvt_bf16x2(p[4], p[5]);
        uint32_t h3 = cvt_bf16x2(p[6], p[7]);
        Ph[u] = make_uint4(h0, h1, h2, h3);
        uint32_t l0 = cvt_bf16x2(p[0] - bf_lo_f(h0), p[1] - bf_hi_f(h0));
        uint32_t l1 = cvt_bf16x2(p[2] - bf_lo_f(h1), p[3] - bf_hi_f(h1));
        uint32_t l2 = cvt_bf16x2(p[4] - bf_lo_f(h2), p[5] - bf_hi_f(h2));
        uint32_t l3 = cvt_bf16x2(p[6] - bf_lo_f(h3), p[7] - bf_hi_f(h3));
        Pl[u] = make_uint4(l0, l1, l2, l3);
    }
}

// ---------------------------------------------------------------------------
// kernel_launch
// ---------------------------------------------------------------------------
static inline void run_split(const float* src, __nv_bfloat16* hi, __nv_bfloat16* lo, size_t n) {
    int n8 = (int)(n >> 3);
    split8<<<(n8 + 1023) / 1024, 256>>>((const float4*)src, (uint4*)hi, (uint4*)lo, n8);
}

extern "C" void kernel_launch(void* const* d_in, const int* in_sizes, int n_in,
                              void* d_out, int out_size)
{
    const float* X   = (const float*)d_in[0];   // [4096,4096]
    const float* upw = (const float*)d_in[1];   // [1024,4096]
    const float* gw  = (const float*)d_in[2];   // [1024,4096]
    const float* lp  = (const float*)d_in[3];   // [1024]
    const float* lao = (const float*)d_in[4];   // [4096,1024]
    const float* fw  = (const float*)d_in[5];   // [4096,6144]
    const float* df  = (const float*)d_in[6];   // [6]
    const float* fgw = (const float*)d_in[7];   // [9984,4096]
    const float* fuw = (const float*)d_in[8];   // [9984,4096]
    const float* fdw = (const float*)d_in[9];   // [4096,9984]
    float* out       = (float*)d_out;           // [4096,4096]

    cudaFuncSetAttribute(tc_gemm<0>, cudaFuncAttributeMaxDynamicSharedMemorySize, SMEM_TOTAL);
    cudaFuncSetAttribute(tc_gemm<1>, cudaFuncAttributeMaxDynamicSharedMemorySize, SMEM_TOTAL);

#define SYM(p, s) cudaGetSymbolAddress((void**)&p, s)
    __nv_bfloat16 *Xh, *Xl, *upwh, *upwl, *gwh, *gwl, *laoh, *laol, *fwh, *fwl;
    __nv_bfloat16 *fgwh, *fgwl, *fuwh, *fuwl, *fdwh, *fdwl;
    __nv_bfloat16 *AUh, *AUl, *TMPh, *TMPl, *Ph, *Pl;
    float *AU, *GP, *BG, *BU;
    SYM(Xh, g_Xhi);   SYM(Xl, g_Xlo);
    SYM(upwh, g_upwh); SYM(upwl, g_upwl);
    SYM(gwh, g_gwh);   SYM(gwl, g_gwl);
    SYM(laoh, g_laoh); SYM(laol, g_laol);
    SYM(fwh, g_fwh);   SYM(fwl, g_fwl);
    SYM(fgwh, g_fgwh); SYM(fgwl, g_fgwl);
    SYM(fuwh, g_fuwh); SYM(fuwl, g_fuwl);
    SYM(fdwh, g_fdwh); SYM(fdwl, g_fdwl);
    SYM(AU, g_AU);     SYM(GP, g_GP);
    SYM(AUh, g_AUh);   SYM(AUl, g_AUl);
    SYM(TMPh, g_TMPh); SYM(TMPl, g_TMPl);
    SYM(BG, g_BG);     SYM(BU, g_BU);
    SYM(Ph, g_Ph);     SYM(Pl, g_Pl);
#undef SYM

    // --- fp32 -> hi/lo bf16 conversions ---
    run_split(X,   Xh,   Xl,   (size_t)NTOK * HDIM);
    run_split(upw, upwh, upwl, (size_t)SDIM * HDIM);
    run_split(gw,  gwh,  gwl,  (size_t)SDIM * HDIM);
    run_split(lao, laoh, laol, (size_t)HDIM * SDIM);
    run_split(fw,  fwh,  fwl,  (size_t)HDIM * KTAY);
    run_split(fgw, fgwh, fgwl, (size_t)FDIM * HDIM);
    run_split(fuw, fuwh, fuwl, (size_t)FDIM * HDIM);
    run_split(fdw, fdwh, fdwl, (size_t)HDIM * FDIM);

    // 1,2: AU = X @ up_w^T ; GP = X @ gate_w^T          [4096,1024], K=4096
    tc_gemm<0><<<dim3(SDIM / 128, NTOK / 128), 256, SMEM_TOTAL>>>(Xh, Xl, upwh, upwl, AU, SDIM, HDIM);
    tc_gemm<0><<<dim3(SDIM / 128, NTOK / 128), 256, SMEM_TOTAL>>>(Xh, Xl, gwh,  gwl,  GP, SDIM, HDIM);

    // 3: AU -> hi/lo ; Taylor coefficients -> TMP hi/lo
    run_split(AU, AUh, AUl, (size_t)NTOK * SDIM);
    taylor_kernel<<<(NTOK * SDIM) / 256, 256>>>(AU, GP, lp, df, TMPh, TMPl);

    // 4: out = AU @ lao^T                                [4096,4096], K=1024
    tc_gemm<0><<<dim3(HDIM / 128, NTOK / 128), 256, SMEM_TOTAL>>>(AUh, AUl, laoh, laol, out, HDIM, SDIM);

    // 5: out += TMP @ fw^T                               [4096,4096], K=6144
    tc_gemm<1><<<dim3(HDIM / 128, NTOK / 128), 256, SMEM_TOTAL>>>(TMPh, TMPl, fwh, fwl, out, HDIM, KTAY);

    // 6,7: FFN gate / up                                 [4096,9984], K=4096
    tc_gemm<0><<<dim3(FDIM / 128, NTOK / 128), 256, SMEM_TOTAL>>>(Xh, Xl, fgwh, fgwl, BG, FDIM, HDIM);
    tc_gemm<0><<<dim3(FDIM / 128, NTOK / 128), 256, SMEM_TOTAL>>>(Xh, Xl, fuwh, fuwl, BU, FDIM, HDIM);

    // 8: P = silu(G) * U -> hi/lo
    {
        int n8 = (int)(((size_t)NTOK * FDIM) >> 3);
        silu_split8<<<(n8 + 511) / 512, 256>>>((const float4*)BG, (const float4*)BU,
                                               (uint4*)Ph, (uint4*)Pl, n8);
    }

    // 9: out += P @ down^T                               [4096,4096], K=9984
    tc_gemm<1><<<dim3(HDIM / 128, NTOK / 128), 256, SMEM_TOTAL>>>(Ph, Pl, fdwh, fdwl, out, HDIM, FDIM);
}

// round 12
// speedup vs baseline: 1.0151x; 1.0151x over previous
#include <cuda_runtime.h>
#include <cuda_bf16.h>
#include <cstdint>

// ---------------------------------------------------------------------------
// Shapes (fixed)
// ---------------------------------------------------------------------------
#define NTOK 4096            // B*T
#define HDIM 4096
#define SDIM 1024
#define FDIM 9984
#define KTAY 6144            // S*G

// ---------------------------------------------------------------------------
// Scratch (__device__ globals; allocation-free)
// ---------------------------------------------------------------------------
__device__ __nv_bfloat16 g_Xhi [NTOK * HDIM], g_Xlo [NTOK * HDIM];
__device__ __nv_bfloat16 g_upwh[SDIM * HDIM], g_upwl[SDIM * HDIM];
__device__ __nv_bfloat16 g_gwh [SDIM * HDIM], g_gwl [SDIM * HDIM];
__device__ __nv_bfloat16 g_laoh[HDIM * SDIM], g_laol[HDIM * SDIM];
__device__ __nv_bfloat16 g_fwh [HDIM * KTAY], g_fwl [HDIM * KTAY];
__device__ __nv_bfloat16 g_fgwh[(size_t)FDIM * HDIM], g_fgwl[(size_t)FDIM * HDIM];
__device__ __nv_bfloat16 g_fuwh[(size_t)FDIM * HDIM], g_fuwl[(size_t)FDIM * HDIM];
__device__ __nv_bfloat16 g_fdwh[(size_t)HDIM * FDIM], g_fdwl[(size_t)HDIM * FDIM];
__device__ float         g_AU  [NTOK * SDIM], g_GP  [NTOK * SDIM];
__device__ __nv_bfloat16 g_AUh [NTOK * SDIM], g_AUl [NTOK * SDIM];
__device__ __nv_bfloat16 g_TMPh[NTOK * KTAY], g_TMPl[NTOK * KTAY];
__device__ float         g_BG  [(size_t)NTOK * FDIM], g_BU[(size_t)NTOK * FDIM];
__device__ __nv_bfloat16 g_Ph  [(size_t)NTOK * FDIM], g_Pl[(size_t)NTOK * FDIM];

// ---------------------------------------------------------------------------
// Baseline-PTX helpers
// ---------------------------------------------------------------------------
__device__ __forceinline__ uint32_t smem_u32(const void* p) {
    uint32_t a;
    asm("{ .reg .u64 t; cvta.to.shared.u64 t, %1; cvt.u32.u64 %0, t; }" : "=r"(a) : "l"(p));
    return a;
}
__device__ __forceinline__ void cpasync16(uint32_t dst, const void* src) {
    asm volatile("cp.async.cg.shared.global [%0], [%1], 16;" :: "r"(dst), "l"(src) : "memory");
}
__device__ __forceinline__ void cp_commit() {
    asm volatile("cp.async.commit_group;" ::: "memory");
}
template <int N>
__device__ __forceinline__ void cp_wait() {
    asm volatile("cp.async.wait_group %0;" :: "n"(N) : "memory");
}
__device__ __forceinline__ void ldm4(uint32_t* r, uint32_t a) {
    asm volatile("ldmatrix.sync.aligned.m8n8.x4.shared.b16 {%0,%1,%2,%3}, [%4];"
                 : "=r"(r[0]), "=r"(r[1]), "=r"(r[2]), "=r"(r[3]) : "r"(a));
}
__device__ __forceinline__ void mma16816(float* d, const uint32_t* a, uint32_t b0, uint32_t b1) {
    asm volatile("mma.sync.aligned.m16n8k16.row.col.f32.bf16.bf16.f32 "
                 "{%0,%1,%2,%3}, {%4,%5,%6,%7}, {%8,%9}, {%0,%1,%2,%3};"
                 : "+f"(d[0]), "+f"(d[1]), "+f"(d[2]), "+f"(d[3])
                 : "r"(a[0]), "r"(a[1]), "r"(a[2]), "r"(a[3]), "r"(b0), "r"(b1));
}
// packed fp32 -> bf16x2
__device__ __forceinline__ uint32_t cvt_bf16x2(float lo_el, float hi_el) {
    uint32_t r;
    asm("cvt.rn.bf16x2.f32 %0, %1, %2;" : "=r"(r) : "f"(hi_el), "f"(lo_el));
    return r;
}
__device__ __forceinline__ float bf_lo_f(uint32_t p) { return __uint_as_float(p << 16); }
__device__ __forceinline__ float bf_hi_f(uint32_t p) { return __uint_as_float(p & 0xffff0000u); }

// ---------------------------------------------------------------------------
// Split-bf16 tensor-core GEMM: C[N=4096, M] (+)= A[.,K] @ B[M,K]^T
// 3-pass: D = Ah*Bh + Ah*Bl + Al*Bh, fp32 accum (~1.7e-4 end-to-end).
// (2-pass measured 1.74e-3 in R10 -> over threshold; do not re-enable.)
// CTA tile 128x128, BK=32, 256 threads (8 warps, 2x4), warp tile 64x32.
// 3-stage cp.async ring, ONE __syncthreads per k-block, 2 CTAs/SM.
// SMEM: unpadded 64B rows + XOR swizzle (chunk' = chunk ^ ((row>>1)&3)).
// NEW (R12):
//  - panel-swizzled CTA mapping (panel width 8 in bx, by-fastest inside):
//    one wave covers ~one panel column -> B-slab per wave fits L2.
//  - DUAL mode: one launch serves two (B, C) pairs sharing A (bx >= msplit
//    selects the second pair) -- merges the two small S-dim projections.
// Requires M%128==0, K%32==0.
// ---------------------------------------------------------------------------
#define BK        32
#define ROWB      64
#define SA_HI     0
#define SA_LO     (128 * ROWB)
#define SB_HI     (2 * 128 * ROWB)
#define SB_LO     (3 * 128 * ROWB)
#define STAGE_B   (4 * 128 * ROWB)         // 32768
#define NSTAGE    3
#define SMEM_TOTAL (NSTAGE * STAGE_B)      // 98304 (x2 CTAs = 192KB)
#define PANEL_W   8

template <int BETA, int DUAL>
__global__ void __launch_bounds__(256, 2)
tc_gemm(const __nv_bfloat16* __restrict__ Ahi, const __nv_bfloat16* __restrict__ Alo,
        const __nv_bfloat16* __restrict__ Bhi, const __nv_bfloat16* __restrict__ Blo,
        float* __restrict__ C, int M, int K,
        const __nv_bfloat16* __restrict__ Bhi2, const __nv_bfloat16* __restrict__ Blo2,
        float* __restrict__ C2, int msplit)
{
    extern __shared__ char smem[];
    const uint32_t sb = smem_u32(smem);
    const int t    = threadIdx.x;
    const int lane = t & 31;
    const int w    = t >> 5;
    const int wm   = w >> 2;
    const int wn   = w & 3;

    // ---- panel-swizzled CTA mapping ----
    int bx, by;
    {
        const int gx = gridDim.x, gy = gridDim.y;
        int bid = blockIdx.y * gx + blockIdx.x;
        int fp  = gx / PANEL_W;            // full panels
        int rem = gx - fp * PANEL_W;
        int cf  = fp * PANEL_W * gy;
        if (bid < cf) {
            int p = bid / (PANEL_W * gy);
            int r = bid - p * (PANEL_W * gy);
            bx = p * PANEL_W + (r % PANEL_W);
            by = r / PANEL_W;
        } else {
            int r = bid - cf;
            bx = fp * PANEL_W + (r % rem);
            by = r / rem;
        }
    }

    const __nv_bfloat16* BhS = Bhi;
    const __nv_bfloat16* BlS = Blo;
    float* CS = C;
    if (DUAL && bx >= msplit) {
        BhS = Bhi2; BlS = Blo2; CS = C2; bx -= msplit;
    }

    const size_t rs = (size_t)K * 2;
    const char* Ah = (const char*)Ahi + (size_t)by * 128 * rs;
    const char* Al = (const char*)Alo + (size_t)by * 128 * rs;
    const char* Bh = (const char*)BhS + (size_t)bx * 128 * rs;
    const char* Bl = (const char*)BlS + (size_t)bx * 128 * rs;

    const int KB = K / BK;

    int r0 = t >> 2, c0 = t & 3;
    int r1 = r0 + 64;
    int cs = c0 ^ ((r0 >> 1) & 3);
    uint32_t so0 = (uint32_t)r0 * ROWB + cs * 16;
    uint32_t so1 = (uint32_t)r1 * ROWB + cs * 16;
    size_t   go0 = (size_t)r0 * rs + c0 * 16;
    size_t   go1 = (size_t)r1 * rs + c0 * 16;

#define LOAD_STAGE(kb, buf)                                                  \
    do {                                                                     \
        uint32_t st = sb + (uint32_t)(buf) * STAGE_B;                        \
        size_t   kofs = (size_t)(kb) * 64;                                   \
        cpasync16(st + SA_HI + so0, Ah + go0 + kofs);                        \
        cpasync16(st + SA_HI + so1, Ah + go1 + kofs);                        \
        cpasync16(st + SA_LO + so0, Al + go0 + kofs);                        \
        cpasync16(st + SA_LO + so1, Al + go1 + kofs);                        \
        cpasync16(st + SB_HI + so0, Bh + go0 + kofs);                        \
        cpasync16(st + SB_HI + so1, Bh + go1 + kofs);                        \
        cpasync16(st + SB_LO + so0, Bl + go0 + kofs);                        \
        cpasync16(st + SB_LO + so1, Bl + go1 + kofs);                        \
        cp_commit();                                                         \
    } while (0)

    const int la_r  = lane & 15;
    const int la_sw = (la_r >> 1) & 3;
    const int la_c  = lane >> 4;
    const int lb_r  = (lane & 7) + ((lane >> 4) << 3);
    const int lb_sw = (lb_r >> 1) & 3;
    const int lb_c  = (lane >> 3) & 1;

    float acc[4][4][4];
#pragma unroll
    for (int mi = 0; mi < 4; mi++)
#pragma unroll
        for (int ni = 0; ni < 4; ni++)
#pragma unroll
            for (int q = 0; q < 4; q++) acc[mi][ni][q] = 0.f;

    LOAD_STAGE(0, 0);
    LOAD_STAGE(1, 1);

    int buf = 0, nbuf = 2;
    for (int kb = 0; kb < KB; kb++) {
        if (kb + 1 < KB) cp_wait<1>(); else cp_wait<0>();
        __syncthreads();
        if (kb + 2 < KB) LOAD_STAGE(kb + 2, nbuf);

        const uint32_t st = sb + (uint32_t)buf * STAGE_B;
#pragma unroll
        for (int kk = 0; kk < 2; kk++) {
            const uint32_t ca = (uint32_t)((kk * 2 + la_c) ^ la_sw) * 16;
            const uint32_t cb = (uint32_t)((kk * 2 + lb_c) ^ lb_sw) * 16;
            uint32_t bhf[2][4], blf[2][4];
#pragma unroll
            for (int pr = 0; pr < 2; pr++) {
                uint32_t base = (uint32_t)(wn * 32 + pr * 16 + lb_r) * ROWB + cb;
                ldm4(bhf[pr], st + SB_HI + base);
                ldm4(blf[pr], st + SB_LO + base);
            }
#pragma unroll
            for (int mi = 0; mi < 4; mi++) {
                uint32_t ah[4], al[4];
                uint32_t base = (uint32_t)(wm * 64 + mi * 16 + la_r) * ROWB + ca;
                ldm4(ah, st + SA_HI + base);
                ldm4(al, st + SA_LO + base);
#pragma unroll
                for (int ni = 0; ni < 4; ni++) {
                    const int pr = ni >> 1, hf = (ni & 1) * 2;
                    mma16816(acc[mi][ni], ah, bhf[pr][hf], bhf[pr][hf + 1]);
                    mma16816(acc[mi][ni], ah, blf[pr][hf], blf[pr][hf + 1]);
                    mma16816(acc[mi][ni], al, bhf[pr][hf], bhf[pr][hf + 1]);
                }
            }
        }
        buf  = (buf  == 2) ? 0 : buf + 1;
        nbuf = (nbuf == 2) ? 0 : nbuf + 1;
    }

    // ---- epilogue ----
    const int erow = by * 128 + wm * 64 + (lane >> 2);
    const int ecol = bx * 128 + wn * 32 + (lane & 3) * 2;
#pragma unroll
    for (int mi = 0; mi < 4; mi++) {
#pragma unroll
        for (int ni = 0; ni < 4; ni++) {
            float* p0 = CS + (size_t)(erow + mi * 16) * M + ecol + ni * 8;
            float* p1 = p0 + 8 * M;
            float2 v0 = make_float2(acc[mi][ni][0], acc[mi][ni][1]);
            float2 v1 = make_float2(acc[mi][ni][2], acc[mi][ni][3]);
            if (BETA) {
                float2 o0 = *(float2*)p0, o1 = *(float2*)p1;
                v0.x += o0.x; v0.y += o0.y;
                v1.x += o1.x; v1.y += o1.y;
            }
            *(float2*)p0 = v0;
            *(float2*)p1 = v1;
        }
    }
#undef LOAD_STAGE
}

// ---------------------------------------------------------------------------
// fp32 -> (hi, lo) bf16 split. Unit = 2 float4 (8 elems); 4 units/thread.
// ---------------------------------------------------------------------------
__global__ void split8(const float4* __restrict__ src,
                       uint4* __restrict__ hi, uint4* __restrict__ lo, int n8)
{
    int u0 = blockIdx.x * (blockDim.x * 4) + threadIdx.x;
    float4 a[4], b[4];
    bool   ok[4];
#pragma unroll
    for (int j = 0; j < 4; j++) {
        int u = u0 + j * 256;
        ok[j] = (u < n8);
        if (ok[j]) { a[j] = src[2 * (size_t)u]; b[j] = src[2 * (size_t)u + 1]; }
    }
#pragma unroll
    for (int j = 0; j < 4; j++) {
        if (!ok[j]) continue;
        int u = u0 + j * 256;
        uint32_t h0 = cvt_bf16x2(a[j].x, a[j].y);
        uint32_t h1 = cvt_bf16x2(a[j].z, a[j].w);
        uint32_t h2 = cvt_bf16x2(b[j].x, b[j].y);
        uint32_t h3 = cvt_bf16x2(b[j].z, b[j].w);
        hi[u] = make_uint4(h0, h1, h2, h3);
        uint32_t l0 = cvt_bf16x2(a[j].x - bf_lo_f(h0), a[j].y - bf_hi_f(h0));
        uint32_t l1 = cvt_bf16x2(a[j].z - bf_lo_f(h1), a[j].w - bf_hi_f(h1));
        uint32_t l2 = cvt_bf16x2(b[j].x - bf_lo_f(h2), b[j].y - bf_hi_f(h2));
        uint32_t l3 = cvt_bf16x2(b[j].z - bf_lo_f(h3), b[j].w - bf_hi_f(h3));
        lo[u] = make_uint4(l0, l1, l2, l3);
    }
}

// ---------------------------------------------------------------------------
// Taylor coefficients -> split bf16 TMP[t, s*6+g]
// ---------------------------------------------------------------------------
__global__ void taylor_kernel(const float* __restrict__ AU, const float* __restrict__ GP,
                              const float* __restrict__ lp, const float* __restrict__ df,
                              __nv_bfloat16* __restrict__ TMPh, __nv_bfloat16* __restrict__ TMPl)
{
    int idx = blockIdx.x * blockDim.x + threadIdx.x;    // t*1024 + s
    if (idx >= NTOK * SDIM) return;
    int s = idx & (SDIM - 1);

    float au    = AU[idx];
    float delta = GP[idx] - lp[s];
    float neg   = (delta > 0.f) ? 1.f : -1.f;
    float ad    = fabsf(delta);
    float ld    = logf(ad);
    float keep  = (ad <= 2.5f) ? 1.f : 0.f;

    float v[6];
#pragma unroll
    for (int g = 0; g < 6; g++) {
        int   m = g + 1;
        float dterm = expf(ld * (float)m - df[g]);
        if (m & 1) dterm *= neg;
        float x = dterm * au;
        if (m > 4) x *= keep;
        v[g] = x;
    }
    uint32_t h[3], l[3];
#pragma unroll
    for (int q = 0; q < 3; q++) {
        h[q] = cvt_bf16x2(v[2 * q], v[2 * q + 1]);
        l[q] = cvt_bf16x2(v[2 * q] - bf_lo_f(h[q]), v[2 * q + 1] - bf_hi_f(h[q]));
    }
    uint32_t* ph = (uint32_t*)(TMPh + (size_t)idx * 6);
    uint32_t* pl = (uint32_t*)(TMPl + (size_t)idx * 6);
    ph[0] = h[0]; ph[1] = h[1]; ph[2] = h[2];
    pl[0] = l[0]; pl[1] = l[1]; pl[2] = l[2];
}

// ---------------------------------------------------------------------------
// P = silu(G) * U -> split bf16. Unit = 2 float4; 2 units/thread.
// ---------------------------------------------------------------------------
__global__ void silu_split8(const float4* __restrict__ G, const float4* __restrict__ U,
                            uint4* __restrict__ Ph, uint4* __restrict__ Pl, int n8)
{
    int u0 = blockIdx.x * (blockDim.x * 2) + threadIdx.x;
    float4 g[2][2], uu[2][2];
    bool   ok[2];
#pragma unroll
    for (int j = 0; j < 2; j++) {
        int u = u0 + j * 256;
        ok[j] = (u < n8);
        if (ok[j]) {
            g[j][0]  = G[2 * (size_t)u];     g[j][1]  = G[2 * (size_t)u + 1];
            uu[j][0] = U[2 * (size_t)u];     uu[j][1] = U[2 * (size_t)u + 1];
        }
    }
#pragma unroll
    for (int j = 0; j < 2; j++) {
        if (!ok[j]) continue;
        int u = u0 + j * 256;
        float p[8];
#pragma unroll
        for (int h = 0; h < 2; h++) {
            p[h * 4 + 0] = g[j][h].x / (1.f + expf(-g[j][h].x)) * uu[j][h].x;
            p[h * 4 + 1] = g[j][h].y / (1.f + expf(-g[j][h].y)) * uu[j][h].y;
            p[h * 4 + 2] = g[j][h].z / (1.f + expf(-g[j][h].z)) * uu[j][h].z;
            p[h * 4 + 3] = g[j][h].w / (1.f + expf(-g[j][h].w)) * uu[j][h].w;
        }
        uint32_t h0 = cvt_bf16x2(p[0], p[1]);
        uint32_t h1 = cvt_bf16x2(p[2], p[3]);
        uint32_t h2 = cvt_bf16x2(p[4], p[5]);
        uint32_t h3 = cvt_bf16x2(p[6], p[7]);
        Ph[u] = make_uint4(h0, h1, h2, h3);
        uint32_t l0 = cvt_bf16x2(p[0] - bf_lo_f(h0), p[1] - bf_hi_f(h0));
        uint32_t l1 = cvt_bf16x2(p[2] - bf_lo_f(h1), p[3] - bf_hi_f(h1));
        uint32_t l2 = cvt_bf16x2(p[4] - bf_lo_f(h2), p[5] - bf_hi_f(h2));
        uint32_t l3 = cvt_bf16x2(p[6] - bf_lo_f(h3), p[7] - bf_hi_f(h3));
        Pl[u] = make_uint4(l0, l1, l2, l3);
    }
}

// ---------------------------------------------------------------------------
// kernel_launch
// ---------------------------------------------------------------------------
static inline void run_split(const float* src, __nv_bfloat16* hi, __nv_bfloat16* lo, size_t n) {
    int n8 = (int)(n >> 3);
    split8<<<(n8 + 1023) / 1024, 256>>>((const float4*)src, (uint4*)hi, (uint4*)lo, n8);
}

extern "C" void kernel_launch(void* const* d_in, const int* in_sizes, int n_in,
                              void* d_out, int out_size)
{
    const float* X   = (const float*)d_in[0];   // [4096,4096]
    const float* upw = (const float*)d_in[1];   // [1024,4096]
    const float* gw  = (const float*)d_in[2];   // [1024,4096]
    const float* lp  = (const float*)d_in[3];   // [1024]
    const float* lao = (const float*)d_in[4];   // [4096,1024]
    const float* fw  = (const float*)d_in[5];   // [4096,6144]
    const float* df  = (const float*)d_in[6];   // [6]
    const float* fgw = (const float*)d_in[7];   // [9984,4096]
    const float* fuw = (const float*)d_in[8];   // [9984,4096]
    const float* fdw = (const float*)d_in[9];   // [4096,9984]
    float* out       = (float*)d_out;           // [4096,4096]

    cudaFuncSetAttribute(tc_gemm<0, 0>, cudaFuncAttributeMaxDynamicSharedMemorySize, SMEM_TOTAL);
    cudaFuncSetAttribute(tc_gemm<1, 0>, cudaFuncAttributeMaxDynamicSharedMemorySize, SMEM_TOTAL);
    cudaFuncSetAttribute(tc_gemm<0, 1>, cudaFuncAttributeMaxDynamicSharedMemorySize, SMEM_TOTAL);

#define SYM(p, s) cudaGetSymbolAddress((void**)&p, s)
    __nv_bfloat16 *Xh, *Xl, *upwh, *upwl, *gwh, *gwl, *laoh, *laol, *fwh, *fwl;
    __nv_bfloat16 *fgwh, *fgwl, *fuwh, *fuwl, *fdwh, *fdwl;
    __nv_bfloat16 *AUh, *AUl, *TMPh, *TMPl, *Ph, *Pl;
    float *AU, *GP, *BG, *BU;
    SYM(Xh, g_Xhi);   SYM(Xl, g_Xlo);
    SYM(upwh, g_upwh); SYM(upwl, g_upwl);
    SYM(gwh, g_gwh);   SYM(gwl, g_gwl);
    SYM(laoh, g_laoh); SYM(laol, g_laol);
    SYM(fwh, g_fwh);   SYM(fwl, g_fwl);
    SYM(fgwh, g_fgwh); SYM(fgwl, g_fgwl);
    SYM(fuwh, g_fuwh); SYM(fuwl, g_fuwl);
    SYM(fdwh, g_fdwh); SYM(fdwl, g_fdwl);
    SYM(AU, g_AU);     SYM(GP, g_GP);
    SYM(AUh, g_AUh);   SYM(AUl, g_AUl);
    SYM(TMPh, g_TMPh); SYM(TMPl, g_TMPl);
    SYM(BG, g_BG);     SYM(BU, g_BU);
    SYM(Ph, g_Ph);     SYM(Pl, g_Pl);
#undef SYM

    // --- fp32 -> hi/lo bf16 conversions ---
    run_split(X,   Xh,   Xl,   (size_t)NTOK * HDIM);
    run_split(upw, upwh, upwl, (size_t)SDIM * HDIM);
    run_split(gw,  gwh,  gwl,  (size_t)SDIM * HDIM);
    run_split(lao, laoh, laol, (size_t)HDIM * SDIM);
    run_split(fw,  fwh,  fwl,  (size_t)HDIM * KTAY);
    run_split(fgw, fgwh, fgwl, (size_t)FDIM * HDIM);
    run_split(fuw, fuwh, fuwl, (size_t)FDIM * HDIM);
    run_split(fdw, fdwh, fdwl, (size_t)HDIM * FDIM);

    // 1+2 merged: AU = X @ up_w^T and GP = X @ gate_w^T in one launch
    // grid (16, 32): bx<8 -> (upw, AU), bx>=8 -> (gw, GP). K=4096, M=1024.
    tc_gemm<0, 1><<<dim3(2 * SDIM / 128, NTOK / 128), 256, SMEM_TOTAL>>>(
        Xh, Xl, upwh, upwl, AU, SDIM, HDIM, gwh, gwl, GP, SDIM / 128);

    // 3: AU -> hi/lo ; Taylor coefficients -> TMP hi/lo
    run_split(AU, AUh, AUl, (size_t)NTOK * SDIM);
    taylor_kernel<<<(NTOK * SDIM) / 256, 256>>>(AU, GP, lp, df, TMPh, TMPl);

    // 4: out = AU @ lao^T                                [4096,4096], K=1024
    tc_gemm<0, 0><<<dim3(HDIM / 128, NTOK / 128), 256, SMEM_TOTAL>>>(
        AUh, AUl, laoh, laol, out, HDIM, SDIM, nullptr, nullptr, nullptr, 0);

    // 5: out += TMP @ fw^T                               [4096,4096], K=6144
    tc_gemm<1, 0><<<dim3(HDIM / 128, NTOK / 128), 256, SMEM_TOTAL>>>(
        TMPh, TMPl, fwh, fwl, out, HDIM, KTAY, nullptr, nullptr, nullptr, 0);

    // 6,7: FFN gate / up                                 [4096,9984], K=4096
    tc_gemm<0, 0><<<dim3(FDIM / 128, NTOK / 128), 256, SMEM_TOTAL>>>(
        Xh, Xl, fgwh, fgwl, BG, FDIM, HDIM, nullptr, nullptr, nullptr, 0);
    tc_gemm<0, 0><<<dim3(FDIM / 128, NTOK / 128), 256, SMEM_TOTAL>>>(
        Xh, Xl, fuwh, fuwl, BU, FDIM, HDIM, nullptr, nullptr, nullptr, 0);

    // 8: P = silu(G) * U -> hi/lo
    {
        int n8 = (int)(((size_t)NTOK * FDIM) >> 3);
        silu_split8<<<(n8 + 511) / 512, 256>>>((const float4*)BG, (const float4*)BU,
                                               (uint4*)Ph, (uint4*)Pl, n8);
    }

    // 9: out += P @ down^T                               [4096,4096], K=9984
    tc_gemm<1, 0><<<dim3(HDIM / 128, NTOK / 128), 256, SMEM_TOTAL>>>(
        Ph, Pl, fdwh, fdwl, out, HDIM, FDIM, nullptr, nullptr, nullptr, 0);
}